// round 4
// baseline (speedup 1.0000x reference)
#include <cuda_runtime.h>

// ---------------------------------------------------------------------------
// Problem constants
//   B=512, NQ=10, NA=4, T=16, DEG=4, LAYERS=2, F=64, NROTS=80, QFF_NROTS=40
//   DQ=1024, DW=16384
// State layout: full index i (14 bits): q = i >> 4 (10-bit query, qubit Q at
// bit 9-Q), t = i & 15 (ancilla, wire 10+a at bit 3-a).
// In-warp query layout: q = r*32 + lane  (r = register index 0..31).
//   Qubit Q<=4  -> register bit (4-Q).   Qubit Q>=5 -> lane bit (9-Q).
// ---------------------------------------------------------------------------

#define BATCH 512

// Scratch (static device arrays; no allocation)
__device__ float2 g_cs[BATCH * 16 * 80]; // (cos,sin) of half-angles per (b,t,gate)
__device__ float2 g_M[3 * 256];          // M_k = U_prep * P_{k+1} * U_prep^dag
__device__ float2 g_qffcs[40];           // qff half-angle (cos,sin)
__device__ float2 g_v0[16];              // e^{i phi0} * U_prep[:,0]

static __device__ __forceinline__ float2 cmulf(float2 a, float2 b) {
    return make_float2(a.x * b.x - a.y * b.y, a.x * b.y + a.y * b.x);
}

// ---------------------------------------------------------------------------
// Register-resident gates on the 10-qubit query state (per warp, per t-slice)
// ---------------------------------------------------------------------------

template <int Q>
static __device__ __forceinline__ void ry_g(float2* s, float c, float sn, int lane) {
    if constexpr (Q <= 4) {
        constexpr int M = 1 << (4 - Q);
#pragma unroll
        for (int r = 0; r < 32; ++r)
            if (!(r & M)) {
                float2 a = s[r], b = s[r | M];
                s[r]     = make_float2(fmaf(c, a.x, -sn * b.x), fmaf(c, a.y, -sn * b.y));
                s[r | M] = make_float2(fmaf(sn, a.x, c * b.x), fmaf(sn, a.y, c * b.y));
            }
    } else {
        constexpr int L = 1 << (9 - Q);
        const float t = (lane & L) ? sn : -sn;
#pragma unroll
        for (int r = 0; r < 32; ++r) {
            float ox = __shfl_xor_sync(0xffffffffu, s[r].x, L);
            float oy = __shfl_xor_sync(0xffffffffu, s[r].y, L);
            s[r].x = fmaf(c, s[r].x, t * ox);
            s[r].y = fmaf(c, s[r].y, t * oy);
        }
    }
}

// crx(control C, target T): where control bit == 1 apply rx = [[c,-is],[-is,c]]
// own' = c*own + s*(other.y, -other.x)   (same formula on both sides of pair)
template <int C, int TQ>
static __device__ __forceinline__ void crx_g(float2* s, float c, float sn, int lane) {
    if constexpr (C <= 4 && TQ <= 4) {
        constexpr int MC = 1 << (4 - C), MT = 1 << (4 - TQ);
#pragma unroll
        for (int r = 0; r < 32; ++r)
            if ((r & MC) && !(r & MT)) {
                float2 a = s[r], b = s[r | MT];
                s[r]      = make_float2(fmaf(c, a.x, sn * b.y), fmaf(c, a.y, -sn * b.x));
                s[r | MT] = make_float2(fmaf(c, b.x, sn * a.y), fmaf(c, b.y, -sn * a.x));
            }
    } else if constexpr (C <= 4 && TQ >= 5) {
        constexpr int MC = 1 << (4 - C), LT = 1 << (9 - TQ);
#pragma unroll
        for (int r = 0; r < 32; ++r)
            if (r & MC) {  // compile-time per r: shfl is warp-uniform
                float ox = __shfl_xor_sync(0xffffffffu, s[r].x, LT);
                float oy = __shfl_xor_sync(0xffffffffu, s[r].y, LT);
                s[r].x = fmaf(c, s[r].x, sn * oy);
                s[r].y = fmaf(c, s[r].y, -sn * ox);
            }
    } else if constexpr (C >= 5 && TQ <= 4) {
        constexpr int LC = 1 << (9 - C), MT = 1 << (4 - TQ);
        const bool act = (lane & LC) != 0;
#pragma unroll
        for (int r = 0; r < 32; ++r)
            if (!(r & MT)) {
                if (act) {
                    float2 a = s[r], b = s[r | MT];
                    s[r]      = make_float2(fmaf(c, a.x, sn * b.y), fmaf(c, a.y, -sn * b.x));
                    s[r | MT] = make_float2(fmaf(c, b.x, sn * a.y), fmaf(c, b.y, -sn * a.x));
                }
            }
    } else {
        constexpr int LC = 1 << (9 - C), LT = 1 << (9 - TQ);
        const bool act = (lane & LC) != 0;
#pragma unroll
        for (int r = 0; r < 32; ++r) {
            float ox = __shfl_xor_sync(0xffffffffu, s[r].x, LT);
            float oy = __shfl_xor_sync(0xffffffffu, s[r].y, LT);
            if (act) {
                s[r].x = fmaf(c, s[r].x, sn * oy);
                s[r].y = fmaf(c, s[r].y, -sn * ox);
            }
        }
    }
}

// sim14 single layer, nq=10. Gate order (forward), idx relative to layer base:
//  ry q=0..9 (0-9); crx (9,0)(8,9)(7,8)(6,7)(5,6)(4,5)(3,4)(2,3)(1,2)(0,1) (10-19);
//  ry q=0..9 (20-29); crx (9,8)(0,9)(1,0)(2,1)(3,2)(4,3)(5,4)(6,5)(7,6)(8,7) (30-39)
#define GATES_FWD(RYM, CRXM)                                                     \
    RYM(0, 0) RYM(1, 1) RYM(2, 2) RYM(3, 3) RYM(4, 4)                            \
    RYM(5, 5) RYM(6, 6) RYM(7, 7) RYM(8, 8) RYM(9, 9)                            \
    CRXM(9, 0, 10) CRXM(8, 9, 11) CRXM(7, 8, 12) CRXM(6, 7, 13) CRXM(5, 6, 14)  \
    CRXM(4, 5, 15) CRXM(3, 4, 16) CRXM(2, 3, 17) CRXM(1, 2, 18) CRXM(0, 1, 19)  \
    RYM(0, 20) RYM(1, 21) RYM(2, 22) RYM(3, 23) RYM(4, 24)                       \
    RYM(5, 25) RYM(6, 26) RYM(7, 27) RYM(8, 28) RYM(9, 29)                       \
    CRXM(9, 8, 30) CRXM(0, 9, 31) CRXM(1, 0, 32) CRXM(2, 1, 33) CRXM(3, 2, 34)  \
    CRXM(4, 3, 35) CRXM(5, 4, 36) CRXM(6, 5, 37) CRXM(7, 6, 38) CRXM(8, 7, 39)

#define GATES_ADJ(RYM, CRXM)                                                     \
    CRXM(8, 7, 39) CRXM(7, 6, 38) CRXM(6, 5, 37) CRXM(5, 4, 36) CRXM(4, 3, 35)  \
    CRXM(3, 2, 34) CRXM(2, 1, 33) CRXM(1, 0, 32) CRXM(0, 9, 31) CRXM(9, 8, 30)  \
    RYM(9, 29) RYM(8, 28) RYM(7, 27) RYM(6, 26) RYM(5, 25)                       \
    RYM(4, 24) RYM(3, 23) RYM(2, 22) RYM(1, 21) RYM(0, 20)                       \
    CRXM(0, 1, 19) CRXM(1, 2, 18) CRXM(2, 3, 17) CRXM(3, 4, 16) CRXM(4, 5, 15)  \
    CRXM(5, 6, 14) CRXM(6, 7, 13) CRXM(7, 8, 12) CRXM(8, 9, 11) CRXM(9, 0, 10)  \
    RYM(9, 9) RYM(8, 8) RYM(7, 7) RYM(6, 6) RYM(5, 5)                            \
    RYM(4, 4) RYM(3, 3) RYM(2, 2) RYM(1, 1) RYM(0, 0)

static __device__ __forceinline__ void run_layer_fwd(float2* s, const float2* cs, int lane) {
#define RYM(Q, I)      { float2 g = cs[I]; ry_g<Q>(s, g.x, g.y, lane); }
#define CRXM(C, T, I)  { float2 g = cs[I]; crx_g<C, T>(s, g.x, g.y, lane); }
    GATES_FWD(RYM, CRXM)
#undef RYM
#undef CRXM
}

static __device__ __forceinline__ void run_layer_adj(float2* s, const float2* cs, int lane) {
#define RYM(Q, I)      { float2 g = cs[I]; ry_g<Q>(s, g.x, -g.y, lane); }
#define CRXM(C, T, I)  { float2 g = cs[I]; crx_g<C, T>(s, g.x, -g.y, lane); }
    GATES_ADJ(RYM, CRXM)
#undef RYM
#undef CRXM
}

// ---------------------------------------------------------------------------
// Expectation values: per query qubit Q compute x=2Re(a), y=2Im(a), z
// where a = sum conj(s0)*s1 over pairs differing in qubit Q.
// ---------------------------------------------------------------------------
template <int Q>
static __device__ __forceinline__ void expval_q(const float2* s, int lane, float* acc) {
    float ax = 0.f, ay = 0.f, z = 0.f;
    if constexpr (Q <= 4) {
        constexpr int M = 1 << (4 - Q);
#pragma unroll
        for (int r = 0; r < 32; ++r)
            if (!(r & M)) {
                float2 a = s[r], b = s[r | M];
                ax = fmaf(a.x, b.x, fmaf(a.y, b.y, ax));
                ay = fmaf(a.x, b.y, fmaf(-a.y, b.x, ay));
                z  = fmaf(a.x, a.x, fmaf(a.y, a.y, fmaf(-b.x, b.x, fmaf(-b.y, b.y, z))));
            }
    } else {
        constexpr int L = 1 << (9 - Q);
        const bool lo = (lane & L) == 0;
#pragma unroll
        for (int r = 0; r < 32; ++r) {
            float ox = __shfl_xor_sync(0xffffffffu, s[r].x, L);
            float oy = __shfl_xor_sync(0xffffffffu, s[r].y, L);
            float n = fmaf(s[r].x, s[r].x, s[r].y * s[r].y);
            if (lo) {
                ax = fmaf(s[r].x, ox, fmaf(s[r].y, oy, ax));
                ay = fmaf(s[r].x, oy, fmaf(-s[r].y, ox, ay));
                z += n;
            } else {
                z -= n;
            }
        }
    }
#pragma unroll
    for (int off = 16; off; off >>= 1) {
        ax += __shfl_xor_sync(0xffffffffu, ax, off);
        ay += __shfl_xor_sync(0xffffffffu, ay, off);
        z  += __shfl_xor_sync(0xffffffffu, z, off);
    }
    if (lane == 0) {
        atomicAdd(&acc[Q], 2.f * ax);
        atomicAdd(&acc[10 + Q], 2.f * ay);
        atomicAdd(&acc[20 + Q], z);
    }
}

// ---------------------------------------------------------------------------
// Setup kernel: build U_prep (16x16), v0, M_k, qff cos/sin. One block, 256 thr.
// ---------------------------------------------------------------------------
__global__ void qts_setup(const float* __restrict__ prep, const float* __restrict__ sig,
                          const float* __restrict__ qff) {
    __shared__ float2 U[16][16];  // U[row][col]
    int tid = threadIdx.x;

    if (tid < 16) {
        // Evolve column `tid` of the prepare unitary
        float2 v[16];
        for (int t = 0; t < 16; ++t) v[t] = make_float2(t == tid ? 1.f : 0.f, 0.f);
        for (int ly = 0; ly < 4; ++ly) {
            for (int qi = 0; qi < 4; ++qi) {
                int bb = 3 - qi;  // ancilla bit of wire 10+qi
                int m = 1 << bb;
                // ry
                float th = prep[(ly * 4 + qi) * 2 + 0];
                float c, sn;
                sincosf(0.5f * th, &sn, &c);
                for (int j = 0; j < 16; ++j)
                    if (!(j & m)) {
                        float2 a0 = v[j], a1 = v[j | m];
                        v[j]     = make_float2(c * a0.x - sn * a1.x, c * a0.y - sn * a1.y);
                        v[j | m] = make_float2(sn * a0.x + c * a1.x, sn * a0.y + c * a1.y);
                    }
                // rz: diag(e^{-i th/2}, e^{+i th/2})
                th = prep[(ly * 4 + qi) * 2 + 1];
                sincosf(0.5f * th, &sn, &c);
                float2 e0 = make_float2(c, -sn), e1 = make_float2(c, sn);
                for (int j = 0; j < 16; ++j) v[j] = cmulf(v[j], (j & m) ? e1 : e0);
            }
            for (int i = 0; i < 3; ++i) {  // cnot(ctrl wire 10+i, tgt wire 11+i)
                int cm = 1 << (3 - i), tm = 1 << (2 - i);
                for (int j = 0; j < 16; ++j)
                    if ((j & cm) && !(j & tm)) {
                        float2 tmp = v[j];
                        v[j] = v[j | tm];
                        v[j | tm] = tmp;
                    }
            }
        }
        for (int t = 0; t < 16; ++t) U[t][tid] = v[t];
    }
    __syncthreads();

    if (tid < 16) {
        float c, sn;
        sincosf(sig[0], &sn, &c);
        g_v0[tid] = cmulf(make_float2(c, sn), U[tid][0]);
    }
    if (tid < 40) {
        float c, sn;
        sincosf(0.5f * qff[tid], &sn, &c);
        g_qffcs[tid] = make_float2(c, sn);
    }
    {
        int tp = tid >> 4, t = tid & 15;
        for (int m = 0; m < 3; ++m) {
            float c, sn;
            sincosf(sig[m + 1], &sn, &c);
            float2 acc = make_float2(0.f, 0.f);
            for (int si = 0; si < 16; ++si) {
                float2 P = (si == 0) ? make_float2(c, sn) : make_float2(c, -sn);
                float2 u = U[tp][si];
                float2 uc = make_float2(U[t][si].x, -U[t][si].y);
                float2 p = cmulf(cmulf(u, P), uc);
                acc.x += p.x;
                acc.y += p.y;
            }
            g_M[m * 256 + tp * 16 + t] = acc;
        }
    }
}

// ---------------------------------------------------------------------------
// Projection kernel: h = (x^T + pe) @ W^T + b ; angle = 2*pi*sigmoid(h);
// store (cos, sin) of angle/2. One block per batch, 256 threads.
// ---------------------------------------------------------------------------
__global__ void qts_proj(const float* __restrict__ x, const float* __restrict__ Wp,
                         const float* __restrict__ bp) {
    __shared__ float xe[16][64];   // x[b]^T + positional encoding
    __shared__ float WsT[64][80];  // W transposed: [f][j]
    int b = blockIdx.x, tid = threadIdx.x;

    for (int i = tid; i < 80 * 64; i += 256) {
        int j = i / 64, f = i % 64;
        WsT[f][j] = Wp[i];
    }
    const float kdiv = -0.14391156831212787f;  // -ln(10000)/64
    for (int i = tid; i < 1024; i += 256) {
        int f = i >> 4, t = i & 15;
        float arg = (float)t * expf(kdiv * (float)(f & ~1));
        float pe = (f & 1) ? cosf(arg) : sinf(arg);
        xe[t][f] = x[b * 1024 + i] + pe;
    }
    __syncthreads();

    for (int o = tid; o < 1280; o += 256) {
        int t = o / 80, j = o % 80;
        float h = bp[j];
#pragma unroll 16
        for (int f = 0; f < 64; ++f) h = fmaf(xe[t][f], WsT[f][j], h);
        // half-angle = pi * sigmoid(h)
        float half = 3.14159265358979323846f / (1.0f + expf(-h));
        float c, sn;
        sincosf(half, &sn, &c);
        g_cs[b * 1280 + o] = make_float2(c, sn);
    }
}

// ---------------------------------------------------------------------------
// Main kernel: one CTA per batch element. 16 warps; warp w owns ancilla t=w.
// ---------------------------------------------------------------------------
__global__ __launch_bounds__(512, 1) void qts_main(const float* __restrict__ Wout,
                                                   const float* __restrict__ bout,
                                                   float* __restrict__ out) {
    extern __shared__ char smem_raw[];
    float2* buf  = (float2*)smem_raw;  // [16][1024] state buffer (131072 B)
    float2* sa   = buf + 16384;        // [16][80] angles (10240 B)
    float2* sM   = sa + 1280;          // [3][16][16] mix matrices (6144 B)
    float2* sqff = sM + 768;           // [40]
    float2* sv0  = sqff + 40;          // [16]
    float* acc   = (float*)(sv0 + 16); // [32]

    const int tid = threadIdx.x, b = blockIdx.x;
    const int w = tid >> 5, lane = tid & 31;

    for (int i = tid; i < 1280; i += 512) sa[i] = g_cs[b * 1280 + i];
    for (int i = tid; i < 768; i += 512) sM[i] = g_M[i];
    if (tid < 40) sqff[tid] = g_qffcs[tid];
    if (tid < 16) sv0[tid] = g_v0[tid];
    if (tid < 30) acc[tid] = 0.f;
    __syncthreads();

    // Initial state: amplitude v0[t] at query index 0
    float2 s[32];
#pragma unroll
    for (int r = 0; r < 32; ++r) s[r] = make_float2(0.f, 0.f);
    if (lane == 0) s[0] = sv0[w];

    const float2* cs = sa + w * 80;

#pragma unroll 1
    for (int k = 0; k < 4; ++k) {
        const bool adj = (k & 1) != 0;
        // Two sim14 layers; forward order (layer 0 then 1), adjoint reversed.
#pragma unroll 1
        for (int l = 0; l < 2; ++l) {
            const float2* lcs = cs + (adj ? (1 - l) : l) * 40;
            if (adj) run_layer_adj(s, lcs, lane);
            else     run_layer_fwd(s, lcs, lane);
        }
        if (k < 3) {
            // 16x16 ancilla mix: M_{k} applied across t for every q
#pragma unroll
            for (int r = 0; r < 32; ++r) buf[w * 1024 + r * 32 + lane] = s[r];
            __syncthreads();
            const float2* Mk = sM + k * 256;
#pragma unroll 1
            for (int half = 0; half < 2; ++half) {
                int q = w * 64 + half * 32 + lane;  // this (lane,half) owns column q
                float2 in[16];
#pragma unroll
                for (int t = 0; t < 16; ++t) in[t] = buf[t * 1024 + q];
#pragma unroll
                for (int tp = 0; tp < 16; ++tp) {
                    float2 a = make_float2(0.f, 0.f);
#pragma unroll
                    for (int t = 0; t < 16; ++t) {
                        float2 m = Mk[tp * 16 + t];
                        a.x = fmaf(m.x, in[t].x, fmaf(-m.y, in[t].y, a.x));
                        a.y = fmaf(m.x, in[t].y, fmaf(m.y, in[t].x, a.y));
                    }
                    buf[tp * 1024 + q] = a;
                }
            }
            __syncthreads();
#pragma unroll
            for (int r = 0; r < 32; ++r) s[r] = buf[w * 1024 + r * 32 + lane];
        }
    }

    // qff: one sim14 layer on query qubits, shared params
    run_layer_fwd(s, sqff, lane);

    // Expectation values (per-warp partials -> smem accumulate)
    expval_q<0>(s, lane, acc);
    expval_q<1>(s, lane, acc);
    expval_q<2>(s, lane, acc);
    expval_q<3>(s, lane, acc);
    expval_q<4>(s, lane, acc);
    expval_q<5>(s, lane, acc);
    expval_q<6>(s, lane, acc);
    expval_q<7>(s, lane, acc);
    expval_q<8>(s, lane, acc);
    expval_q<9>(s, lane, acc);
    __syncthreads();

    if (tid == 0) {
        float o = bout[0];
#pragma unroll
        for (int i = 0; i < 30; ++i) o = fmaf(acc[i], Wout[i], o);
        out[b] = o;
    }
}

// ---------------------------------------------------------------------------
extern "C" void kernel_launch(void* const* d_in, const int* in_sizes, int n_in,
                              void* d_out, int out_size) {
    (void)in_sizes; (void)n_in; (void)out_size;
    const float* x    = (const float*)d_in[0];  // (512, 64, 16)
    const float* Wp   = (const float*)d_in[1];  // (80, 64)
    const float* bp   = (const float*)d_in[2];  // (80,)
    const float* prep = (const float*)d_in[3];  // (4, 4, 2)
    const float* sig  = (const float*)d_in[4];  // (5,)
    const float* qff  = (const float*)d_in[5];  // (40,)
    const float* Wout = (const float*)d_in[6];  // (1, 30)
    const float* bout = (const float*)d_in[7];  // (1,)
    float* out = (float*)d_out;                 // (512,)

    size_t smem = (16384 + 1280 + 768 + 40 + 16) * sizeof(float2) + 32 * sizeof(float);
    cudaFuncSetAttribute(qts_main, cudaFuncAttributeMaxDynamicSharedMemorySize, (int)smem);

    qts_setup<<<1, 256>>>(prep, sig, qff);
    qts_proj<<<BATCH, 256>>>(x, Wp, bp);
    qts_main<<<BATCH, 512, smem>>>(Wout, bout, out);
}

// round 5
// speedup vs baseline: 2.7921x; 2.7921x over previous
#include <cuda_runtime.h>

// ---------------------------------------------------------------------------
// B=512, NQ=10, NA=4, T=16, DEG=4, LAYERS=2, F=64, NROTS=80, QFF_NROTS=40
// State: 14 bits: q = i>>4 (query qubit Q at bit 9-Q), t = i&15 (wire 10+a at
// bit 3-a). In-warp: q = r*32+lane. Qubit Q<=4 -> reg bit (4-Q); Q>=5 -> lane
// bit (9-Q). Amplitudes packed (re,im) in 64-bit f32x2 registers.
// ---------------------------------------------------------------------------

#define BATCH 512

typedef unsigned long long f2x;

__device__ float2 g_cs[BATCH * 1280];   // (cos,sin) half-angles per (b,t,gate)
__device__ ulonglong2 g_Mpk[3 * 256];   // packed mix matrices: {(m.x,m.x),(m.y,m.y)}
__device__ float2 g_qffcs[40];
__device__ float2 g_v0[16];

// ---- f32x2 primitives ------------------------------------------------------
static __device__ __forceinline__ f2x f2pack(float lo, float hi) {
    f2x r; asm("mov.b64 %0, {%1, %2};" : "=l"(r) : "f"(lo), "f"(hi)); return r;
}
static __device__ __forceinline__ void f2unpack(f2x v, float& lo, float& hi) {
    asm("mov.b64 {%0, %1}, %2;" : "=f"(lo), "=f"(hi) : "l"(v));
}
static __device__ __forceinline__ f2x f2fma(f2x a, f2x b, f2x c) {
    f2x r; asm("fma.rn.f32x2 %0, %1, %2, %3;" : "=l"(r) : "l"(a), "l"(b), "l"(c)); return r;
}
static __device__ __forceinline__ f2x f2mul(f2x a, f2x b) {
    f2x r; asm("mul.rn.f32x2 %0, %1, %2;" : "=l"(r) : "l"(a), "l"(b)); return r;
}
static __device__ __forceinline__ f2x f2swap(f2x v) {
    float lo, hi; f2unpack(v, lo, hi); return f2pack(hi, lo);
}
static __device__ __forceinline__ f2x f2shfl(f2x v, int m) {
    float lo, hi; f2unpack(v, lo, hi);
    lo = __shfl_xor_sync(0xffffffffu, lo, m);
    hi = __shfl_xor_sync(0xffffffffu, hi, m);
    return f2pack(lo, hi);
}
static __device__ __forceinline__ f2x f2shflswap(f2x v, int m) {
    float lo, hi; f2unpack(v, lo, hi);
    lo = __shfl_xor_sync(0xffffffffu, lo, m);
    hi = __shfl_xor_sync(0xffffffffu, hi, m);
    return f2pack(hi, lo);
}
static __device__ __forceinline__ float2 cmulf(float2 a, float2 b) {
    return make_float2(a.x * b.x - a.y * b.y, a.x * b.y + a.y * b.x);
}

// ---- gates (state: f2x s[32] per lane) -------------------------------------
// ry: new_a = c*a - s*b ; new_b = s*a + c*b   (coeffs real, both components)
template <int Q>
static __device__ __forceinline__ void ry_g(f2x* s, f2x cc, f2x sp, f2x ns, int lane) {
    if constexpr (Q <= 4) {
        constexpr int M = 1 << (4 - Q);
#pragma unroll
        for (int r = 0; r < 32; ++r)
            if (!(r & M)) {
                f2x a = s[r], b = s[r | M];
                s[r]     = f2fma(cc, a, f2mul(ns, b));
                s[r | M] = f2fma(cc, b, f2mul(sp, a));
            }
    } else {
        constexpr int L = 1 << (9 - Q);
        const f2x t = (lane & L) ? sp : ns;
#pragma unroll
        for (int r = 0; r < 32; ++r) {
            f2x o = f2shfl(s[r], L);
            s[r] = f2fma(cc, s[r], f2mul(t, o));
        }
    }
}

// crx (ctrl=1): new = c*own + sn*(other.y, -other.x).
// pk = (sn, -sn); pk (x) swap(other) = (sn*o.y, -sn*o.x).
// Lane-control variants gate via per-lane coefficients (cc,pk)->(1,0): branch-free.
template <int C, int TQ>
static __device__ __forceinline__ void crx_g(f2x* s, f2x cc, f2x pk, int lane) {
    if constexpr (C <= 4 && TQ <= 4) {
        constexpr int MC = 1 << (4 - C), MT = 1 << (4 - TQ);
#pragma unroll
        for (int r = 0; r < 32; ++r)
            if ((r & MC) && !(r & MT)) {
                f2x a = s[r], b = s[r | MT];
                s[r]      = f2fma(cc, a, f2mul(pk, f2swap(b)));
                s[r | MT] = f2fma(cc, b, f2mul(pk, f2swap(a)));
            }
    } else if constexpr (C <= 4 && TQ >= 5) {
        constexpr int MC = 1 << (4 - C), LT = 1 << (9 - TQ);
#pragma unroll
        for (int r = 0; r < 32; ++r)
            if (r & MC) {  // compile-time per r: shfl stays warp-uniform
                f2x osw = f2shflswap(s[r], LT);
                s[r] = f2fma(cc, s[r], f2mul(pk, osw));
            }
    } else if constexpr (C >= 5 && TQ <= 4) {
        constexpr int LC = 1 << (9 - C), MT = 1 << (4 - TQ);
        const bool act = (lane & LC) != 0;
        const f2x cc2 = act ? cc : f2pack(1.f, 1.f);
        const f2x pk2 = act ? pk : 0ull;
#pragma unroll
        for (int r = 0; r < 32; ++r)
            if (!(r & MT)) {
                f2x a = s[r], b = s[r | MT];
                s[r]      = f2fma(cc2, a, f2mul(pk2, f2swap(b)));
                s[r | MT] = f2fma(cc2, b, f2mul(pk2, f2swap(a)));
            }
    } else {
        constexpr int LC = 1 << (9 - C), LT = 1 << (9 - TQ);
        const bool act = (lane & LC) != 0;
        const f2x cc2 = act ? cc : f2pack(1.f, 1.f);
        const f2x pk2 = act ? pk : 0ull;
#pragma unroll
        for (int r = 0; r < 32; ++r) {
            f2x osw = f2shflswap(s[r], LT);
            s[r] = f2fma(cc2, s[r], f2mul(pk2, osw));
        }
    }
}

// sim14 layer gate lists (validated in round 4)
#define GATES_FWD(RYM, CRXM)                                                     \
    RYM(0, 0) RYM(1, 1) RYM(2, 2) RYM(3, 3) RYM(4, 4)                            \
    RYM(5, 5) RYM(6, 6) RYM(7, 7) RYM(8, 8) RYM(9, 9)                            \
    CRXM(9, 0, 10) CRXM(8, 9, 11) CRXM(7, 8, 12) CRXM(6, 7, 13) CRXM(5, 6, 14)  \
    CRXM(4, 5, 15) CRXM(3, 4, 16) CRXM(2, 3, 17) CRXM(1, 2, 18) CRXM(0, 1, 19)  \
    RYM(0, 20) RYM(1, 21) RYM(2, 22) RYM(3, 23) RYM(4, 24)                       \
    RYM(5, 25) RYM(6, 26) RYM(7, 27) RYM(8, 28) RYM(9, 29)                       \
    CRXM(9, 8, 30) CRXM(0, 9, 31) CRXM(1, 0, 32) CRXM(2, 1, 33) CRXM(3, 2, 34)  \
    CRXM(4, 3, 35) CRXM(5, 4, 36) CRXM(6, 5, 37) CRXM(7, 6, 38) CRXM(8, 7, 39)

#define GATES_ADJ(RYM, CRXM)                                                     \
    CRXM(8, 7, 39) CRXM(7, 6, 38) CRXM(6, 5, 37) CRXM(5, 4, 36) CRXM(4, 3, 35)  \
    CRXM(3, 2, 34) CRXM(2, 1, 33) CRXM(1, 0, 32) CRXM(0, 9, 31) CRXM(9, 8, 30)  \
    RYM(9, 29) RYM(8, 28) RYM(7, 27) RYM(6, 26) RYM(5, 25)                       \
    RYM(4, 24) RYM(3, 23) RYM(2, 22) RYM(1, 21) RYM(0, 20)                       \
    CRXM(0, 1, 19) CRXM(1, 2, 18) CRXM(2, 3, 17) CRXM(3, 4, 16) CRXM(4, 5, 15)  \
    CRXM(5, 6, 14) CRXM(6, 7, 13) CRXM(7, 8, 12) CRXM(8, 9, 11) CRXM(9, 0, 10)  \
    RYM(9, 9) RYM(8, 8) RYM(7, 7) RYM(6, 6) RYM(5, 5)                            \
    RYM(4, 4) RYM(3, 3) RYM(2, 2) RYM(1, 1) RYM(0, 0)

static __device__ __forceinline__ void run_layer_fwd(f2x* s, const float2* cs, int lane) {
#define RYM(Q, I)                                                                 \
    { float2 g = cs[I];                                                           \
      f2x cc = f2pack(g.x, g.x), sp = f2pack(g.y, g.y), ns = f2pack(-g.y, -g.y);  \
      ry_g<Q>(s, cc, sp, ns, lane); }
#define CRXM(C, T, I)                                                             \
    { float2 g = cs[I];                                                           \
      f2x cc = f2pack(g.x, g.x), pk = f2pack(g.y, -g.y);                          \
      crx_g<C, T>(s, cc, pk, lane); }
    GATES_FWD(RYM, CRXM)
#undef RYM
#undef CRXM
}

static __device__ __forceinline__ void run_layer_adj(f2x* s, const float2* cs, int lane) {
#define RYM(Q, I)                                                                 \
    { float2 g = cs[I];                                                           \
      f2x cc = f2pack(g.x, g.x), sp = f2pack(-g.y, -g.y), ns = f2pack(g.y, g.y);  \
      ry_g<Q>(s, cc, sp, ns, lane); }
#define CRXM(C, T, I)                                                             \
    { float2 g = cs[I];                                                           \
      f2x cc = f2pack(g.x, g.x), pk = f2pack(-g.y, g.y);                          \
      crx_g<C, T>(s, cc, pk, lane); }
    GATES_ADJ(RYM, CRXM)
#undef RYM
#undef CRXM
}

// ---- expectation values ----------------------------------------------------
template <int Q>
static __device__ __forceinline__ void expval_q(const f2x* s, int lane, float* acc) {
    float ax = 0.f, ay = 0.f, z = 0.f;
    if constexpr (Q <= 4) {
        constexpr int M = 1 << (4 - Q);
#pragma unroll
        for (int r = 0; r < 32; ++r)
            if (!(r & M)) {
                float axr, ayr, bxr, byr;
                f2unpack(s[r], axr, ayr);
                f2unpack(s[r | M], bxr, byr);
                ax = fmaf(axr, bxr, fmaf(ayr, byr, ax));
                ay = fmaf(axr, byr, fmaf(-ayr, bxr, ay));
                z  = fmaf(axr, axr, fmaf(ayr, ayr, fmaf(-bxr, bxr, fmaf(-byr, byr, z))));
            }
    } else {
        constexpr int L = 1 << (9 - Q);
        const bool lo = (lane & L) == 0;
#pragma unroll
        for (int r = 0; r < 32; ++r) {
            float x, y;
            f2unpack(s[r], x, y);
            float ox = __shfl_xor_sync(0xffffffffu, x, L);
            float oy = __shfl_xor_sync(0xffffffffu, y, L);
            float n = fmaf(x, x, y * y);
            if (lo) {
                ax = fmaf(x, ox, fmaf(y, oy, ax));
                ay = fmaf(x, oy, fmaf(-y, ox, ay));
                z += n;
            } else {
                z -= n;
            }
        }
    }
#pragma unroll
    for (int off = 16; off; off >>= 1) {
        ax += __shfl_xor_sync(0xffffffffu, ax, off);
        ay += __shfl_xor_sync(0xffffffffu, ay, off);
        z  += __shfl_xor_sync(0xffffffffu, z, off);
    }
    if (lane == 0) {
        atomicAdd(&acc[Q], 2.f * ax);
        atomicAdd(&acc[10 + Q], 2.f * ay);
        atomicAdd(&acc[20 + Q], z);
    }
}

// ---------------------------------------------------------------------------
// Projection kernel (with circuit-constant setup fused into block 0)
// ---------------------------------------------------------------------------
__global__ void qts_proj(const float* __restrict__ x, const float* __restrict__ Wp,
                         const float* __restrict__ bp, const float* __restrict__ prep,
                         const float* __restrict__ sig, const float* __restrict__ qff) {
    __shared__ float xe[16][64];
    __shared__ float WsT[64][80];
    __shared__ float2 U[16][16];
    int b = blockIdx.x, tid = threadIdx.x;

    if (b == 0) {
        // ---- setup: build U_prep, v0, packed M_k, qff cos/sin ----
        if (tid < 16) {
            float2 v[16];
            for (int t = 0; t < 16; ++t) v[t] = make_float2(t == tid ? 1.f : 0.f, 0.f);
            for (int ly = 0; ly < 4; ++ly) {
                for (int qi = 0; qi < 4; ++qi) {
                    int m = 1 << (3 - qi);
                    float th = prep[(ly * 4 + qi) * 2 + 0];
                    float c, sn;
                    sincosf(0.5f * th, &sn, &c);
                    for (int j = 0; j < 16; ++j)
                        if (!(j & m)) {
                            float2 a0 = v[j], a1 = v[j | m];
                            v[j]     = make_float2(c * a0.x - sn * a1.x, c * a0.y - sn * a1.y);
                            v[j | m] = make_float2(sn * a0.x + c * a1.x, sn * a0.y + c * a1.y);
                        }
                    th = prep[(ly * 4 + qi) * 2 + 1];
                    sincosf(0.5f * th, &sn, &c);
                    float2 e0 = make_float2(c, -sn), e1 = make_float2(c, sn);
                    for (int j = 0; j < 16; ++j) v[j] = cmulf(v[j], (j & m) ? e1 : e0);
                }
                for (int i = 0; i < 3; ++i) {
                    int cm = 1 << (3 - i), tm = 1 << (2 - i);
                    for (int j = 0; j < 16; ++j)
                        if ((j & cm) && !(j & tm)) {
                            float2 tmp = v[j]; v[j] = v[j | tm]; v[j | tm] = tmp;
                        }
                }
            }
            for (int t = 0; t < 16; ++t) U[t][tid] = v[t];
        }
        __syncthreads();
        if (tid < 16) {
            float c, sn;
            sincosf(sig[0], &sn, &c);
            g_v0[tid] = cmulf(make_float2(c, sn), U[tid][0]);
        }
        if (tid < 40) {
            float c, sn;
            sincosf(0.5f * qff[tid], &sn, &c);
            g_qffcs[tid] = make_float2(c, sn);
        }
        {
            int tp = tid >> 4, t = tid & 15;
            for (int m = 0; m < 3; ++m) {
                float c, sn;
                sincosf(sig[m + 1], &sn, &c);
                float2 acc = make_float2(0.f, 0.f);
                for (int si = 0; si < 16; ++si) {
                    float2 P = (si == 0) ? make_float2(c, sn) : make_float2(c, -sn);
                    float2 u = U[tp][si];
                    float2 uc = make_float2(U[t][si].x, -U[t][si].y);
                    float2 p = cmulf(cmulf(u, P), uc);
                    acc.x += p.x; acc.y += p.y;
                }
                g_Mpk[m * 256 + tp * 16 + t] =
                    make_ulonglong2(f2pack(acc.x, acc.x), f2pack(acc.y, acc.y));
            }
        }
        __syncthreads();
    }

    // ---- projection (all blocks) ----
    for (int i = tid; i < 80 * 64; i += 256) {
        int j = i / 64, f = i % 64;
        WsT[f][j] = Wp[i];
    }
    const float kdiv = -0.14391156831212787f;  // -ln(10000)/64
    for (int i = tid; i < 1024; i += 256) {
        int f = i >> 4, t = i & 15;
        float arg = (float)t * expf(kdiv * (float)(f & ~1));
        float pe = (f & 1) ? cosf(arg) : sinf(arg);
        xe[t][f] = x[b * 1024 + i] + pe;
    }
    __syncthreads();

    for (int o = tid; o < 1280; o += 256) {
        int t = o / 80, j = o % 80;
        float h = bp[j];
#pragma unroll 16
        for (int f = 0; f < 64; ++f) h = fmaf(xe[t][f], WsT[f][j], h);
        float half = 3.14159265358979323846f / (1.0f + expf(-h));
        float c, sn;
        sincosf(half, &sn, &c);
        g_cs[b * 1280 + o] = make_float2(c, sn);
    }
}

// ---------------------------------------------------------------------------
// Main kernel: one CTA per batch element; warp w owns ancilla slice t=w.
// ---------------------------------------------------------------------------
__global__ __launch_bounds__(512, 1) void qts_main(const float* __restrict__ Wout,
                                                   const float* __restrict__ bout,
                                                   float* __restrict__ out) {
    extern __shared__ char smem_raw[];
    f2x* buf         = (f2x*)smem_raw;                       // [16][1024] packed amps (131072 B)
    ulonglong2* sMpk = (ulonglong2*)(smem_raw + 131072);     // [3][256] packed M (12288 B)
    float2* sa       = (float2*)(smem_raw + 131072 + 12288); // [16][80] angles (10240 B)
    float2* sqff     = sa + 1280;                            // [40]
    float2* sv0      = sqff + 40;                            // [16]
    float* acc       = (float*)(sv0 + 16);                   // [32]

    const int tid = threadIdx.x, b = blockIdx.x;
    const int w = tid >> 5, lane = tid & 31;

    for (int i = tid; i < 1280; i += 512) sa[i] = g_cs[b * 1280 + i];
    for (int i = tid; i < 768; i += 512) sMpk[i] = g_Mpk[i];
    if (tid < 40) sqff[tid] = g_qffcs[tid];
    if (tid < 16) sv0[tid] = g_v0[tid];
    if (tid < 30) acc[tid] = 0.f;
    __syncthreads();

    f2x s[32];
#pragma unroll
    for (int r = 0; r < 32; ++r) s[r] = 0ull;
    if (lane == 0) {
        float2 v = sv0[w];
        s[0] = f2pack(v.x, v.y);
    }

    const float2* cs = sa + w * 80;

#pragma unroll 1
    for (int k = 0; k < 4; ++k) {
        const bool adj = (k & 1) != 0;
#pragma unroll 1
        for (int l = 0; l < 2; ++l) {
            const float2* lcs = cs + (adj ? (1 - l) : l) * 40;
            if (adj) run_layer_adj(s, lcs, lane);
            else     run_layer_fwd(s, lcs, lane);
        }
        if (k < 3) {
            // 16x16 ancilla mix across t for every q (column-owned, race-free)
#pragma unroll
            for (int r = 0; r < 32; ++r) buf[w * 1024 + r * 32 + lane] = s[r];
            __syncthreads();
            const ulonglong2* Mk = sMpk + k * 256;
#pragma unroll 1
            for (int half = 0; half < 2; ++half) {
                int q = w * 64 + half * 32 + lane;
                f2x in[16], insw[16];
#pragma unroll
                for (int t = 0; t < 16; ++t) {
                    in[t] = buf[t * 1024 + q];
                    float ix, iy;
                    f2unpack(in[t], ix, iy);
                    insw[t] = f2pack(-iy, ix);  // i * in (for imaginary part of M)
                }
#pragma unroll
                for (int tp = 0; tp < 16; ++tp) {
                    f2x a = 0ull;
#pragma unroll
                    for (int t = 0; t < 16; ++t) {
                        ulonglong2 m = Mk[tp * 16 + t];
                        a = f2fma(m.x, in[t], a);
                        a = f2fma(m.y, insw[t], a);
                    }
                    buf[tp * 1024 + q] = a;
                }
            }
            __syncthreads();
#pragma unroll
            for (int r = 0; r < 32; ++r) s[r] = buf[w * 1024 + r * 32 + lane];
        }
    }

    // qff: one sim14 layer on query qubits (shared params)
    run_layer_fwd(s, sqff, lane);

    expval_q<0>(s, lane, acc);
    expval_q<1>(s, lane, acc);
    expval_q<2>(s, lane, acc);
    expval_q<3>(s, lane, acc);
    expval_q<4>(s, lane, acc);
    expval_q<5>(s, lane, acc);
    expval_q<6>(s, lane, acc);
    expval_q<7>(s, lane, acc);
    expval_q<8>(s, lane, acc);
    expval_q<9>(s, lane, acc);
    __syncthreads();

    if (tid == 0) {
        float o = bout[0];
#pragma unroll
        for (int i = 0; i < 30; ++i) o = fmaf(acc[i], Wout[i], o);
        out[b] = o;
    }
}

// ---------------------------------------------------------------------------
extern "C" void kernel_launch(void* const* d_in, const int* in_sizes, int n_in,
                              void* d_out, int out_size) {
    (void)in_sizes; (void)n_in; (void)out_size;
    const float* x    = (const float*)d_in[0];  // (512, 64, 16)
    const float* Wp   = (const float*)d_in[1];  // (80, 64)
    const float* bp   = (const float*)d_in[2];  // (80,)
    const float* prep = (const float*)d_in[3];  // (4, 4, 2)
    const float* sig  = (const float*)d_in[4];  // (5,)
    const float* qff  = (const float*)d_in[5];  // (40,)
    const float* Wout = (const float*)d_in[6];  // (1, 30)
    const float* bout = (const float*)d_in[7];  // (1,)
    float* out = (float*)d_out;                 // (512,)

    size_t smem = 131072 + 12288 + 10240 + 40 * 8 + 16 * 8 + 32 * 4;
    cudaFuncSetAttribute(qts_main, cudaFuncAttributeMaxDynamicSharedMemorySize, (int)smem);

    qts_proj<<<BATCH, 256>>>(x, Wp, bp, prep, sig, qff);
    qts_main<<<BATCH, 512, smem>>>(Wout, bout, out);
}

// round 6
// speedup vs baseline: 3.1301x; 1.1210x over previous
#include <cuda_runtime.h>

// ---------------------------------------------------------------------------
// B=512, NQ=10, NA=4, T=16, DEG=4, LAYERS=2, F=64, NROTS=80, QFF_NROTS=40
// State: q = i>>4 (10-bit query), t = i&15 (ancilla). Warp w owns t=w.
// In-warp: 1024 amps, 32 f32x2 regs/lane. ALTERNATING qubit map:
//   qubit Q even -> register bit Q/2 ; qubit Q odd -> lane bit Q/2.
// With this map every sim14 crx (i,i+-1) is cross (one reg, one lane qubit):
// lane-control/reg-target needs NO shuffles (coefficient gating).
// ---------------------------------------------------------------------------

#define BATCH 512

typedef unsigned long long f2x;

__device__ float2 g_cs[BATCH * 1280];   // (cos,sin) half-angles per (b,t,gate)
__device__ ulonglong2 g_Mpk[3 * 256];   // packed mix matrices {(m.x,m.x),(m.y,m.y)}
__device__ float2 g_qffcs[40];
__device__ float2 g_v0[16];

// ---- f32x2 primitives ------------------------------------------------------
static __device__ __forceinline__ f2x f2pack(float lo, float hi) {
    f2x r; asm("mov.b64 %0, {%1, %2};" : "=l"(r) : "f"(lo), "f"(hi)); return r;
}
static __device__ __forceinline__ void f2unpack(f2x v, float& lo, float& hi) {
    asm("mov.b64 {%0, %1}, %2;" : "=f"(lo), "=f"(hi) : "l"(v));
}
static __device__ __forceinline__ f2x f2fma(f2x a, f2x b, f2x c) {
    f2x r; asm("fma.rn.f32x2 %0, %1, %2, %3;" : "=l"(r) : "l"(a), "l"(b), "l"(c)); return r;
}
static __device__ __forceinline__ f2x f2mul(f2x a, f2x b) {
    f2x r; asm("mul.rn.f32x2 %0, %1, %2;" : "=l"(r) : "l"(a), "l"(b)); return r;
}
static __device__ __forceinline__ f2x f2swap(f2x v) {
    float lo, hi; f2unpack(v, lo, hi); return f2pack(hi, lo);
}
static __device__ __forceinline__ f2x f2shfl(f2x v, int m) {
    float lo, hi; f2unpack(v, lo, hi);
    lo = __shfl_xor_sync(0xffffffffu, lo, m);
    hi = __shfl_xor_sync(0xffffffffu, hi, m);
    return f2pack(lo, hi);
}
static __device__ __forceinline__ f2x f2shflswap(f2x v, int m) {
    float lo, hi; f2unpack(v, lo, hi);
    lo = __shfl_xor_sync(0xffffffffu, lo, m);
    hi = __shfl_xor_sync(0xffffffffu, hi, m);
    return f2pack(hi, lo);
}
static __device__ __forceinline__ float2 cmulf(float2 a, float2 b) {
    return make_float2(a.x * b.x - a.y * b.y, a.x * b.y + a.y * b.x);
}

// ---- gates -----------------------------------------------------------------
// ry: new_a = c*a - s*b ; new_b = s*a + c*b
template <int Q>
static __device__ __forceinline__ void ry_g(f2x* s, f2x cc, f2x sp, f2x ns, int lane) {
    if constexpr ((Q & 1) == 0) {       // register qubit, bit Q/2
        constexpr int M = 1 << (Q / 2);
#pragma unroll
        for (int r = 0; r < 32; ++r)
            if (!(r & M)) {
                f2x a = s[r], b = s[r | M];
                s[r]     = f2fma(cc, a, f2mul(ns, b));
                s[r | M] = f2fma(cc, b, f2mul(sp, a));
            }
    } else {                            // lane qubit, bit Q/2
        constexpr int L = 1 << (Q / 2);
        const f2x t = (lane & L) ? sp : ns;
#pragma unroll
        for (int r = 0; r < 32; ++r) {
            f2x o = f2shfl(s[r], L);
            s[r] = f2fma(cc, s[r], f2mul(t, o));
        }
    }
}

// crx (ctrl=1): new = c*own + sn*(other.y, -other.x); pk = (sn, -sn).
// Lane-controlled variants gate via coefficients (cc,pk)->(1,0): branch-free.
template <int C, int TQ>
static __device__ __forceinline__ void crx_g(f2x* s, f2x cc, f2x pk, int lane) {
    if constexpr ((C & 1) == 0 && (TQ & 1) == 0) {       // reg ctrl, reg tgt
        constexpr int MC = 1 << (C / 2), MT = 1 << (TQ / 2);
#pragma unroll
        for (int r = 0; r < 32; ++r)
            if ((r & MC) && !(r & MT)) {
                f2x a = s[r], b = s[r | MT];
                s[r]      = f2fma(cc, a, f2mul(pk, f2swap(b)));
                s[r | MT] = f2fma(cc, b, f2mul(pk, f2swap(a)));
            }
    } else if constexpr ((C & 1) == 0 && (TQ & 1) == 1) { // reg ctrl, lane tgt
        constexpr int MC = 1 << (C / 2), LT = 1 << (TQ / 2);
#pragma unroll
        for (int r = 0; r < 32; ++r)
            if (r & MC) {  // compile-time per r: shfl warp-uniform
                f2x osw = f2shflswap(s[r], LT);
                s[r] = f2fma(cc, s[r], f2mul(pk, osw));
            }
    } else if constexpr ((C & 1) == 1 && (TQ & 1) == 0) { // lane ctrl, reg tgt: NO shfl
        constexpr int LC = 1 << (C / 2), MT = 1 << (TQ / 2);
        const bool act = (lane & LC) != 0;
        const f2x cc2 = act ? cc : f2pack(1.f, 1.f);
        const f2x pk2 = act ? pk : 0ull;
#pragma unroll
        for (int r = 0; r < 32; ++r)
            if (!(r & MT)) {
                f2x a = s[r], b = s[r | MT];
                s[r]      = f2fma(cc2, a, f2mul(pk2, f2swap(b)));
                s[r | MT] = f2fma(cc2, b, f2mul(pk2, f2swap(a)));
            }
    } else {                                              // lane ctrl, lane tgt
        constexpr int LC = 1 << (C / 2), LT = 1 << (TQ / 2);
        const bool act = (lane & LC) != 0;
        const f2x cc2 = act ? cc : f2pack(1.f, 1.f);
        const f2x pk2 = act ? pk : 0ull;
#pragma unroll
        for (int r = 0; r < 32; ++r) {
            f2x osw = f2shflswap(s[r], LT);
            s[r] = f2fma(cc2, s[r], f2mul(pk2, osw));
        }
    }
}

// sim14 layer gate lists (reference order; validated rounds 4-5)
#define GATES_RING1(CRXM)                                                        \
    CRXM(9, 0, 10) CRXM(8, 9, 11) CRXM(7, 8, 12) CRXM(6, 7, 13) CRXM(5, 6, 14)  \
    CRXM(4, 5, 15) CRXM(3, 4, 16) CRXM(2, 3, 17) CRXM(1, 2, 18) CRXM(0, 1, 19)

#define GATES_TAIL(RYM, CRXM)                                                    \
    GATES_RING1(CRXM)                                                            \
    RYM(0, 20) RYM(1, 21) RYM(2, 22) RYM(3, 23) RYM(4, 24)                       \
    RYM(5, 25) RYM(6, 26) RYM(7, 27) RYM(8, 28) RYM(9, 29)                       \
    CRXM(9, 8, 30) CRXM(0, 9, 31) CRXM(1, 0, 32) CRXM(2, 1, 33) CRXM(3, 2, 34)  \
    CRXM(4, 3, 35) CRXM(5, 4, 36) CRXM(6, 5, 37) CRXM(7, 6, 38) CRXM(8, 7, 39)

#define GATES_FWD(RYM, CRXM)                                                     \
    RYM(0, 0) RYM(1, 1) RYM(2, 2) RYM(3, 3) RYM(4, 4)                            \
    RYM(5, 5) RYM(6, 6) RYM(7, 7) RYM(8, 8) RYM(9, 9)                            \
    GATES_TAIL(RYM, CRXM)

#define GATES_ADJ(RYM, CRXM)                                                     \
    CRXM(8, 7, 39) CRXM(7, 6, 38) CRXM(6, 5, 37) CRXM(5, 4, 36) CRXM(4, 3, 35)  \
    CRXM(3, 2, 34) CRXM(2, 1, 33) CRXM(1, 0, 32) CRXM(0, 9, 31) CRXM(9, 8, 30)  \
    RYM(9, 29) RYM(8, 28) RYM(7, 27) RYM(6, 26) RYM(5, 25)                       \
    RYM(4, 24) RYM(3, 23) RYM(2, 22) RYM(1, 21) RYM(0, 20)                       \
    CRXM(0, 1, 19) CRXM(1, 2, 18) CRXM(2, 3, 17) CRXM(3, 4, 16) CRXM(4, 5, 15)  \
    CRXM(5, 6, 14) CRXM(6, 7, 13) CRXM(7, 8, 12) CRXM(8, 9, 11) CRXM(9, 0, 10)  \
    RYM(9, 9) RYM(8, 8) RYM(7, 7) RYM(6, 6) RYM(5, 5)                            \
    RYM(4, 4) RYM(3, 3) RYM(2, 2) RYM(1, 1) RYM(0, 0)

#define RYM_F(Q, I)                                                               \
    { float2 g = cs[I];                                                           \
      f2x cc = f2pack(g.x, g.x), sp = f2pack(g.y, g.y), ns = f2pack(-g.y, -g.y);  \
      ry_g<Q>(s, cc, sp, ns, lane); }
#define CRXM_F(C, T, I)                                                           \
    { float2 g = cs[I];                                                           \
      f2x cc = f2pack(g.x, g.x), pk = f2pack(g.y, -g.y);                          \
      crx_g<C, T>(s, cc, pk, lane); }
#define RYM_A(Q, I)                                                               \
    { float2 g = cs[I];                                                           \
      f2x cc = f2pack(g.x, g.x), sp = f2pack(-g.y, -g.y), ns = f2pack(g.y, g.y);  \
      ry_g<Q>(s, cc, sp, ns, lane); }
#define CRXM_A(C, T, I)                                                           \
    { float2 g = cs[I];                                                           \
      f2x cc = f2pack(g.x, g.x), pk = f2pack(-g.y, g.y);                          \
      crx_g<C, T>(s, cc, pk, lane); }

static __device__ __forceinline__ void run_layer_fwd(f2x* s, const float2* cs, int lane) {
    GATES_FWD(RYM_F, CRXM_F)
}
static __device__ __forceinline__ void run_layer_fwd_tail(f2x* s, const float2* cs, int lane) {
    GATES_TAIL(RYM_F, CRXM_F)
}
static __device__ __forceinline__ void run_layer_adj(f2x* s, const float2* cs, int lane) {
    GATES_ADJ(RYM_A, CRXM_A)
}

// ---- expectation values ----------------------------------------------------
template <int Q>
static __device__ __forceinline__ void expval_q(const f2x* s, int lane, float* acc) {
    float ax = 0.f, ay = 0.f, z = 0.f;
    if constexpr ((Q & 1) == 0) {
        constexpr int M = 1 << (Q / 2);
#pragma unroll
        for (int r = 0; r < 32; ++r)
            if (!(r & M)) {
                float axr, ayr, bxr, byr;
                f2unpack(s[r], axr, ayr);
                f2unpack(s[r | M], bxr, byr);
                ax = fmaf(axr, bxr, fmaf(ayr, byr, ax));
                ay = fmaf(axr, byr, fmaf(-ayr, bxr, ay));
                z  = fmaf(axr, axr, fmaf(ayr, ayr, fmaf(-bxr, bxr, fmaf(-byr, byr, z))));
            }
    } else {
        constexpr int L = 1 << (Q / 2);
        const bool lo = (lane & L) == 0;
#pragma unroll
        for (int r = 0; r < 32; ++r) {
            float x, y;
            f2unpack(s[r], x, y);
            float ox = __shfl_xor_sync(0xffffffffu, x, L);
            float oy = __shfl_xor_sync(0xffffffffu, y, L);
            float n = fmaf(x, x, y * y);
            if (lo) {
                ax = fmaf(x, ox, fmaf(y, oy, ax));
                ay = fmaf(x, oy, fmaf(-y, ox, ay));
                z += n;
            } else {
                z -= n;
            }
        }
    }
#pragma unroll
    for (int off = 16; off; off >>= 1) {
        ax += __shfl_xor_sync(0xffffffffu, ax, off);
        ay += __shfl_xor_sync(0xffffffffu, ay, off);
        z  += __shfl_xor_sync(0xffffffffu, z, off);
    }
    if (lane == 0) {
        atomicAdd(&acc[Q], 2.f * ax);
        atomicAdd(&acc[10 + Q], 2.f * ay);
        atomicAdd(&acc[20 + Q], z);
    }
}

// ---------------------------------------------------------------------------
// Projection kernel (circuit-constant setup fused into block 0)
// ---------------------------------------------------------------------------
__global__ void qts_proj(const float* __restrict__ x, const float* __restrict__ Wp,
                         const float* __restrict__ bp, const float* __restrict__ prep,
                         const float* __restrict__ sig, const float* __restrict__ qff) {
    __shared__ float xe[16][64];
    __shared__ float WsT[64][80];
    __shared__ float2 U[16][16];
    int b = blockIdx.x, tid = threadIdx.x;

    if (b == 0) {
        if (tid < 16) {
            float2 v[16];
            for (int t = 0; t < 16; ++t) v[t] = make_float2(t == tid ? 1.f : 0.f, 0.f);
            for (int ly = 0; ly < 4; ++ly) {
                for (int qi = 0; qi < 4; ++qi) {
                    int m = 1 << (3 - qi);
                    float th = prep[(ly * 4 + qi) * 2 + 0];
                    float c, sn;
                    sincosf(0.5f * th, &sn, &c);
                    for (int j = 0; j < 16; ++j)
                        if (!(j & m)) {
                            float2 a0 = v[j], a1 = v[j | m];
                            v[j]     = make_float2(c * a0.x - sn * a1.x, c * a0.y - sn * a1.y);
                            v[j | m] = make_float2(sn * a0.x + c * a1.x, sn * a0.y + c * a1.y);
                        }
                    th = prep[(ly * 4 + qi) * 2 + 1];
                    sincosf(0.5f * th, &sn, &c);
                    float2 e0 = make_float2(c, -sn), e1 = make_float2(c, sn);
                    for (int j = 0; j < 16; ++j) v[j] = cmulf(v[j], (j & m) ? e1 : e0);
                }
                for (int i = 0; i < 3; ++i) {
                    int cm = 1 << (3 - i), tm = 1 << (2 - i);
                    for (int j = 0; j < 16; ++j)
                        if ((j & cm) && !(j & tm)) {
                            float2 tmp = v[j]; v[j] = v[j | tm]; v[j | tm] = tmp;
                        }
                }
            }
            for (int t = 0; t < 16; ++t) U[t][tid] = v[t];
        }
        __syncthreads();
        if (tid < 16) {
            float c, sn;
            sincosf(sig[0], &sn, &c);
            g_v0[tid] = cmulf(make_float2(c, sn), U[tid][0]);
        }
        if (tid < 40) {
            float c, sn;
            sincosf(0.5f * qff[tid], &sn, &c);
            g_qffcs[tid] = make_float2(c, sn);
        }
        {
            int tp = tid >> 4, t = tid & 15;
            for (int m = 0; m < 3; ++m) {
                float c, sn;
                sincosf(sig[m + 1], &sn, &c);
                float2 acc = make_float2(0.f, 0.f);
                for (int si = 0; si < 16; ++si) {
                    float2 P = (si == 0) ? make_float2(c, sn) : make_float2(c, -sn);
                    float2 u = U[tp][si];
                    float2 uc = make_float2(U[t][si].x, -U[t][si].y);
                    float2 p = cmulf(cmulf(u, P), uc);
                    acc.x += p.x; acc.y += p.y;
                }
                g_Mpk[m * 256 + tp * 16 + t] =
                    make_ulonglong2(f2pack(acc.x, acc.x), f2pack(acc.y, acc.y));
            }
        }
        __syncthreads();
    }

    for (int i = tid; i < 80 * 64; i += 256) {
        int j = i / 64, f = i % 64;
        WsT[f][j] = Wp[i];
    }
    const float kdiv = -0.14391156831212787f;  // -ln(10000)/64
    for (int i = tid; i < 1024; i += 256) {
        int f = i >> 4, t = i & 15;
        float arg = (float)t * expf(kdiv * (float)(f & ~1));
        float pe = (f & 1) ? cosf(arg) : sinf(arg);
        xe[t][f] = x[b * 1024 + i] + pe;
    }
    __syncthreads();

    for (int o = tid; o < 1280; o += 256) {
        int t = o / 80, j = o % 80;
        float h = bp[j];
#pragma unroll 16
        for (int f = 0; f < 64; ++f) h = fmaf(xe[t][f], WsT[f][j], h);
        float half = 3.14159265358979323846f / (1.0f + expf(-h));
        float c, sn;
        sincosf(half, &sn, &c);
        g_cs[b * 1280 + o] = make_float2(c, sn);
    }
}

// ---------------------------------------------------------------------------
// Main kernel
// ---------------------------------------------------------------------------
static __device__ __forceinline__ void ancilla_mix(f2x* s, f2x* buf, const ulonglong2* Mk,
                                                   int w, int lane) {
#pragma unroll
    for (int r = 0; r < 32; ++r) buf[w * 1024 + r * 32 + lane] = s[r];
    __syncthreads();
#pragma unroll 1
    for (int half = 0; half < 2; ++half) {
        int q = w * 64 + half * 32 + lane;
        f2x in[16], insw[16];
#pragma unroll
        for (int t = 0; t < 16; ++t) {
            in[t] = buf[t * 1024 + q];
            float ix, iy;
            f2unpack(in[t], ix, iy);
            insw[t] = f2pack(-iy, ix);  // i * in
        }
#pragma unroll
        for (int tp = 0; tp < 16; ++tp) {
            f2x a = 0ull;
#pragma unroll
            for (int t = 0; t < 16; ++t) {
                ulonglong2 m = Mk[tp * 16 + t];
                a = f2fma(m.x, in[t], a);
                a = f2fma(m.y, insw[t], a);
            }
            buf[tp * 1024 + q] = a;
        }
    }
    __syncthreads();
#pragma unroll
    for (int r = 0; r < 32; ++r) s[r] = buf[w * 1024 + r * 32 + lane];
}

__global__ __launch_bounds__(512, 1) void qts_main(const float* __restrict__ Wout,
                                                   const float* __restrict__ bout,
                                                   float* __restrict__ out) {
    extern __shared__ char smem_raw[];
    f2x* buf         = (f2x*)smem_raw;                       // [16][1024] packed amps
    ulonglong2* sMpk = (ulonglong2*)(smem_raw + 131072);     // [3][256]
    float2* sa       = (float2*)(smem_raw + 131072 + 12288); // [16][80]
    float2* sqff     = sa + 1280;                            // [40]
    float2* sv0      = sqff + 40;                            // [16]
    float* acc       = (float*)(sv0 + 16);                   // [32]

    const int tid = threadIdx.x, b = blockIdx.x;
    const int w = tid >> 5, lane = tid & 31;

    for (int i = tid; i < 1280; i += 512) sa[i] = g_cs[b * 1280 + i];
    for (int i = tid; i < 768; i += 512) sMpk[i] = g_Mpk[i];
    if (tid < 40) sqff[tid] = g_qffcs[tid];
    if (tid < 16) sv0[tid] = g_v0[tid];
    if (tid < 30) acc[tid] = 0.f;
    __syncthreads();

    const float2* cs = sa + w * 80;
    f2x s[32];

    // ---- select k=0, layer 1: first ry block applied to |0...0> gives an
    // exact product state: amp = v0 * prod_Q (bit ? sin : cos). Then tail.
    {
        float lp = 1.f;
#pragma unroll
        for (int j = 0; j < 5; ++j) {        // lane qubits Q = 2j+1
            float2 g = cs[2 * j + 1];
            lp *= ((lane >> j) & 1) ? g.y : g.x;
        }
        float rp[32];
        rp[0] = lp;
#pragma unroll
        for (int j = 0; j < 5; ++j) {        // reg qubits Q = 2j
            float2 g = cs[2 * j];
            int m = 1 << j;
#pragma unroll
            for (int r = 0; r < 32; ++r)
                if (r < m) {
                    rp[r | m] = rp[r] * g.y;
                    rp[r]     = rp[r] * g.x;
                }
        }
        float2 v = sv0[w];
#pragma unroll
        for (int r = 0; r < 32; ++r) s[r] = f2pack(v.x * rp[r], v.y * rp[r]);

        run_layer_fwd_tail(s, cs, lane);
        run_layer_fwd(s, cs + 40, lane);
    }
    ancilla_mix(s, buf, sMpk + 0 * 256, w, lane);

#pragma unroll 1
    for (int k = 1; k < 4; ++k) {
        const bool adj = (k & 1) != 0;
#pragma unroll 1
        for (int l = 0; l < 2; ++l) {
            const float2* lcs = cs + (adj ? (1 - l) : l) * 40;
            if (adj) run_layer_adj(s, lcs, lane);
            else     run_layer_fwd(s, lcs, lane);
        }
        if (k < 3) ancilla_mix(s, buf, sMpk + k * 256, w, lane);
    }

    // qff layer (shared params)
    {
        const float2* cs2 = sqff;
        {
            const float2* cs = cs2;
            run_layer_fwd(s, cs, lane);
        }
    }

    expval_q<0>(s, lane, acc);
    expval_q<1>(s, lane, acc);
    expval_q<2>(s, lane, acc);
    expval_q<3>(s, lane, acc);
    expval_q<4>(s, lane, acc);
    expval_q<5>(s, lane, acc);
    expval_q<6>(s, lane, acc);
    expval_q<7>(s, lane, acc);
    expval_q<8>(s, lane, acc);
    expval_q<9>(s, lane, acc);
    __syncthreads();

    if (tid == 0) {
        float o = bout[0];
#pragma unroll
        for (int i = 0; i < 30; ++i) o = fmaf(acc[i], Wout[i], o);
        out[b] = o;
    }
}

// ---------------------------------------------------------------------------
extern "C" void kernel_launch(void* const* d_in, const int* in_sizes, int n_in,
                              void* d_out, int out_size) {
    (void)in_sizes; (void)n_in; (void)out_size;
    const float* x    = (const float*)d_in[0];  // (512, 64, 16)
    const float* Wp   = (const float*)d_in[1];  // (80, 64)
    const float* bp   = (const float*)d_in[2];  // (80,)
    const float* prep = (const float*)d_in[3];  // (4, 4, 2)
    const float* sig  = (const float*)d_in[4];  // (5,)
    const float* qff  = (const float*)d_in[5];  // (40,)
    const float* Wout = (const float*)d_in[6];  // (1, 30)
    const float* bout = (const float*)d_in[7];  // (1,)
    float* out = (float*)d_out;                 // (512,)

    size_t smem = 131072 + 12288 + 10240 + 40 * 8 + 16 * 8 + 32 * 4;
    cudaFuncSetAttribute(qts_main, cudaFuncAttributeMaxDynamicSharedMemorySize, (int)smem);

    qts_proj<<<BATCH, 256>>>(x, Wp, bp, prep, sig, qff);
    qts_main<<<BATCH, 512, smem>>>(Wout, bout, out);
}